// round 2
// baseline (speedup 1.0000x reference)
#include <cuda_runtime.h>
#include <cuda_bf16.h>
#include <cstdint>

// ---------------- problem constants ----------------
#define BWIN   4096            // B_
#define NTOK   49              // window tokens
#define CDIM   256
#define HEADS  8
#define HD     32
#define MROWS  (BWIN * NTOK)   // 200704
#define NW     64              // mask windows
#define QSCALE 0.17677669529663687f  // 32^-0.5

// ---------------- scratch (device globals; no allocs allowed) ----------------
__device__ float g_q[(size_t)BWIN * HEADS * NTOK * HD];   // [B,H,N,hd], pre-scaled
__device__ float g_k[(size_t)BWIN * HEADS * NTOK * HD];
__device__ float g_v[(size_t)BWIN * HEADS * NTOK * HD];
__device__ float g_att[(size_t)MROWS * CDIM];             // [B_, N, C] attention output

// ---------------- helpers ----------------
__device__ __forceinline__ unsigned tf32_rna(float x) {
    unsigned u;
    asm("cvt.rna.tf32.f32 %0, %1;" : "=r"(u) : "f"(x));
    return u;
}

// ============================================================================
// tf32 tensor-core GEMM:  C[M,N] = A[M,K] * W[N,K]^T + bias[N]
// BM=128, BN=64, BK=32. 256 threads = 8 warps in a 4(m) x 2(n) grid,
// each warp owns a 32x32 sub-tile = 2x4 m16n8k8 mma tiles.
// MODE 0: QKV epilogue (scatter to g_q/g_k/g_v, scale q)
// MODE 1: proj epilogue (reads g_att; writes `out` row-major)
// ============================================================================
template <int MODE>
__global__ __launch_bounds__(256)
void gemm_tf32_kernel(const float* __restrict__ A,
                      const float* __restrict__ W,
                      const float* __restrict__ bias,
                      float* __restrict__ out)
{
    __shared__ float As[128][36];   // tf32-rounded bits, padded stride
    __shared__ float Bs[64][36];

    const float* __restrict__ Ap = (MODE == 0) ? A : (const float*)g_att;

    const int tid  = threadIdx.x;
    const int warp = tid >> 5;
    const int lane = tid & 31;
    const int gID  = lane >> 2;     // groupID
    const int tig  = lane & 3;      // threadID in group
    const int warp_m = (warp & 3) * 32;
    const int warp_n = (warp >> 2) * 32;
    const int m0 = blockIdx.y * 128;
    const int n0 = blockIdx.x * 64;

    float acc[2][4][4];
    #pragma unroll
    for (int a = 0; a < 2; a++)
        #pragma unroll
        for (int b = 0; b < 4; b++)
            #pragma unroll
            for (int c = 0; c < 4; c++) acc[a][b][c] = 0.f;

    for (int k0 = 0; k0 < CDIM; k0 += 32) {
        // --- stage A tile: 128 rows x 32 k (1024 float4 / 256 thr = 4 each) ---
        #pragma unroll
        for (int it = 0; it < 4; it++) {
            int idx = tid + it * 256;
            int r = idx >> 3, c4 = (idx & 7) * 4;
            float4 f = *(const float4*)(Ap + (size_t)(m0 + r) * CDIM + k0 + c4);
            As[r][c4 + 0] = __uint_as_float(tf32_rna(f.x));
            As[r][c4 + 1] = __uint_as_float(tf32_rna(f.y));
            As[r][c4 + 2] = __uint_as_float(tf32_rna(f.z));
            As[r][c4 + 3] = __uint_as_float(tf32_rna(f.w));
        }
        // --- stage B tile: 64 n-rows x 32 k (512 float4 / 256 thr = 2 each) ---
        #pragma unroll
        for (int it = 0; it < 2; it++) {
            int idx = tid + it * 256;
            int r = idx >> 3, c4 = (idx & 7) * 4;
            float4 f = *(const float4*)(W + (size_t)(n0 + r) * CDIM + k0 + c4);
            Bs[r][c4 + 0] = __uint_as_float(tf32_rna(f.x));
            Bs[r][c4 + 1] = __uint_as_float(tf32_rna(f.y));
            Bs[r][c4 + 2] = __uint_as_float(tf32_rna(f.z));
            Bs[r][c4 + 3] = __uint_as_float(tf32_rna(f.w));
        }
        __syncthreads();

        #pragma unroll
        for (int kk = 0; kk < 32; kk += 8) {
            unsigned af[2][4], bf[4][2];
            #pragma unroll
            for (int mi = 0; mi < 2; mi++) {
                int r = warp_m + mi * 16;
                af[mi][0] = __float_as_uint(As[r + gID    ][kk + tig    ]);
                af[mi][1] = __float_as_uint(As[r + gID + 8][kk + tig    ]);
                af[mi][2] = __float_as_uint(As[r + gID    ][kk + tig + 4]);
                af[mi][3] = __float_as_uint(As[r + gID + 8][kk + tig + 4]);
            }
            #pragma unroll
            for (int ni = 0; ni < 4; ni++) {
                int r = warp_n + ni * 8 + gID;
                bf[ni][0] = __float_as_uint(Bs[r][kk + tig    ]);
                bf[ni][1] = __float_as_uint(Bs[r][kk + tig + 4]);
            }
            #pragma unroll
            for (int mi = 0; mi < 2; mi++)
                #pragma unroll
                for (int ni = 0; ni < 4; ni++) {
                    asm volatile(
                        "mma.sync.aligned.m16n8k8.row.col.f32.tf32.tf32.f32 "
                        "{%0,%1,%2,%3}, {%4,%5,%6,%7}, {%8,%9}, {%0,%1,%2,%3};"
                        : "+f"(acc[mi][ni][0]), "+f"(acc[mi][ni][1]),
                          "+f"(acc[mi][ni][2]), "+f"(acc[mi][ni][3])
                        : "r"(af[mi][0]), "r"(af[mi][1]),
                          "r"(af[mi][2]), "r"(af[mi][3]),
                          "r"(bf[ni][0]), "r"(bf[ni][1]));
                }
        }
        __syncthreads();
    }

    // --- epilogue ---
    #pragma unroll
    for (int mi = 0; mi < 2; mi++)
        #pragma unroll
        for (int ni = 0; ni < 4; ni++)
            #pragma unroll
            for (int c = 0; c < 4; c++) {
                int row = m0 + warp_m + mi * 16 + gID + ((c >= 2) ? 8 : 0);
                int col = n0 + warp_n + ni * 8 + 2 * tig + (c & 1);
                float v = acc[mi][ni][c] + bias[col];
                if (MODE == 0) {
                    int part = col >> 8;          // 0=q 1=k 2=v (uniform per block)
                    int cc = col & 255;
                    int h = cc >> 5, d = cc & 31;
                    int b = row / NTOK;
                    int i = row - b * NTOK;
                    if (part == 0) v *= QSCALE;
                    float* dst = (part == 0) ? g_q : (part == 1) ? g_k : g_v;
                    dst[(((size_t)b * HEADS + h) * NTOK + i) * HD + d] = v;
                } else {
                    out[(size_t)row * CDIM + col] = v;
                }
            }
}

// ============================================================================
// Attention: one block per (window b, head h). 64 threads; thread i<49 owns
// score row i. K/V staged in SMEM (broadcast reads), q-row in registers,
// P in SMEM (row stride 49 words = odd -> conflict-free).
// Writes g_att[b, i, h*32+d].
// ============================================================================
__global__ __launch_bounds__(64)
void attn_kernel(const float* __restrict__ mask,
                 const float* __restrict__ bias_table)
{
    __shared__ __align__(16) float ks[NTOK][HD];
    __shared__ __align__(16) float vs[NTOK][HD];
    __shared__ float P[NTOK][NTOK];

    const int b = blockIdx.x;
    const int h = blockIdx.y;
    const int tid = threadIdx.x;

    const size_t base = ((size_t)b * HEADS + h) * NTOK * HD;
    const float4* __restrict__ k4 = (const float4*)(g_k + base);
    const float4* __restrict__ v4 = (const float4*)(g_v + base);
    #pragma unroll
    for (int it = 0; it < (NTOK * HD / 4 + 63) / 64; it++) {
        int idx = tid + it * 64;
        if (idx < NTOK * HD / 4) {
            ((float4*)ks)[idx] = k4[idx];
            ((float4*)vs)[idx] = v4[idx];
        }
    }
    __syncthreads();

    const int i = tid;
    if (i < NTOK) {
        // q row -> registers
        float qr[HD];
        const float4* q4 = (const float4*)(g_q + base + (size_t)i * HD);
        #pragma unroll
        for (int t = 0; t < 8; t++) {
            float4 f = q4[t];
            qr[4*t] = f.x; qr[4*t+1] = f.y; qr[4*t+2] = f.z; qr[4*t+3] = f.w;
        }

        const float* __restrict__ mrow =
            mask + (size_t)(b & (NW - 1)) * (NTOK * NTOK) + i * NTOK;
        const int ci0 = i / 7, ci1 = i - ci0 * 7;

        float mx = -1e30f;
        #pragma unroll 7
        for (int j = 0; j < NTOK; j++) {
            const float4* kr = (const float4*)ks[j];
            float s = 0.f;
            #pragma unroll
            for (int t = 0; t < 8; t++) {
                float4 f = kr[t];
                s += qr[4*t] * f.x + qr[4*t+1] * f.y
                   + qr[4*t+2] * f.z + qr[4*t+3] * f.w;
            }
            int cj0 = j / 7, cj1 = j - cj0 * 7;
            int rel = (ci0 - cj0 + 6) * 13 + (ci1 - cj1 + 6);
            s += __ldg(bias_table + rel * HEADS + h) + __ldg(mrow + j);
            P[i][j] = s;
            mx = fmaxf(mx, s);
        }

        float sum = 0.f;
        #pragma unroll 7
        for (int j = 0; j < NTOK; j++) {
            float e = __expf(P[i][j] - mx);
            P[i][j] = e;
            sum += e;
        }
        float inv = 1.f / sum;

        float o[HD];
        #pragma unroll
        for (int d = 0; d < HD; d++) o[d] = 0.f;
        #pragma unroll 7
        for (int j = 0; j < NTOK; j++) {
            float pj = P[i][j] * inv;
            const float4* vr = (const float4*)vs[j];
            #pragma unroll
            for (int t = 0; t < 8; t++) {
                float4 f = vr[t];
                o[4*t]   += pj * f.x;
                o[4*t+1] += pj * f.y;
                o[4*t+2] += pj * f.z;
                o[4*t+3] += pj * f.w;
            }
        }

        float* optr = g_att + (((size_t)b * NTOK + i) * HEADS + h) * HD;
        #pragma unroll
        for (int t = 0; t < 8; t++)
            ((float4*)optr)[t] = make_float4(o[4*t], o[4*t+1], o[4*t+2], o[4*t+3]);
    }
}

// ============================================================================
// launch
// ============================================================================
extern "C" void kernel_launch(void* const* d_in, const int* in_sizes, int n_in,
                              void* d_out, int out_size)
{
    const float* x          = (const float*)d_in[0];
    const float* mask       = (const float*)d_in[1];
    const float* qkv_w      = (const float*)d_in[2];
    const float* qkv_b      = (const float*)d_in[3];
    const float* proj_w     = (const float*)d_in[4];
    const float* proj_b     = (const float*)d_in[5];
    const float* bias_table = (const float*)d_in[6];
    float* out = (float*)d_out;

    // 1) qkv = x @ qkv_w^T + qkv_b  -> scattered q(scaled)/k/v  [B,H,N,hd]
    gemm_tf32_kernel<0><<<dim3(768 / 64, MROWS / 128), 256>>>(x, qkv_w, qkv_b, nullptr);

    // 2) windowed attention with relative-position bias + mask + softmax
    attn_kernel<<<dim3(BWIN, HEADS), 64>>>(mask, bias_table);

    // 3) out = att @ proj_w^T + proj_b
    gemm_tf32_kernel<1><<<dim3(CDIM / 64, MROWS / 128), 256>>>(nullptr, proj_w, proj_b, out);
}

// round 4
// speedup vs baseline: 1.1973x; 1.1973x over previous
#include <cuda_runtime.h>
#include <cuda_bf16.h>
#include <cstdint>

// ---------------- problem constants ----------------
#define BWIN   4096            // B_
#define NTOK   49              // window tokens
#define CDIM   256
#define HEADS  8
#define HD     32
#define MROWS  (BWIN * NTOK)   // 200704
#define NW     64              // mask windows
#define QSCALE 0.17677669529663687f  // 32^-0.5

// ---------------- scratch (device globals; no allocs allowed) ----------------
__device__ float g_q[(size_t)BWIN * HEADS * NTOK * HD];   // [B,H,N,hd], pre-scaled
__device__ float g_k[(size_t)BWIN * HEADS * NTOK * HD];
__device__ float g_v[(size_t)BWIN * HEADS * NTOK * HD];
__device__ float g_att[(size_t)MROWS * CDIM];             // [B_, N, C]

// ---------------- helpers ----------------
__device__ __forceinline__ unsigned tf32_rna(float x) {
    unsigned u;
    asm("cvt.rna.tf32.f32 %0, %1;" : "=r"(u) : "f"(x));
    return u;
}
__device__ __forceinline__ float4 tf32_rna4(float4 f) {
    f.x = __uint_as_float(tf32_rna(f.x));
    f.y = __uint_as_float(tf32_rna(f.y));
    f.z = __uint_as_float(tf32_rna(f.z));
    f.w = __uint_as_float(tf32_rna(f.w));
    return f;
}
#define MMA_TF32(d0,d1,d2,d3,a0,a1,a2,a3,b0,b1)                                \
    asm volatile("mma.sync.aligned.m16n8k8.row.col.f32.tf32.tf32.f32 "         \
                 "{%0,%1,%2,%3}, {%4,%5,%6,%7}, {%8,%9}, {%0,%1,%2,%3};"       \
                 : "+f"(d0), "+f"(d1), "+f"(d2), "+f"(d3)                      \
                 : "r"(a0), "r"(a1), "r"(a2), "r"(a3), "r"(b0), "r"(b1))

// ============================================================================
// tf32 GEMM:  C[M,N] = A[M,K] * W[N,K]^T + bias[N]
// BM=128, BN=64, BK=32. 256 threads = 8 warps (4m x 2n), warp = 32x32.
// MODE 0: QKV epilogue (scatter q(scaled)/k/v). MODE 1: proj epilogue.
// ============================================================================
template <int MODE>
__global__ __launch_bounds__(256)
void gemm_tf32_kernel(const float* __restrict__ A,
                      const float* __restrict__ W,
                      const float* __restrict__ bias,
                      float* __restrict__ out)
{
    __shared__ float As[128][36];   // 144B row stride (16B aligned)
    __shared__ float Bs[64][36];

    const float* __restrict__ Ap = (MODE == 0) ? A : (const float*)g_att;

    const int tid  = threadIdx.x;
    const int warp = tid >> 5;
    const int lane = tid & 31;
    const int gID  = lane >> 2;
    const int tig  = lane & 3;
    const int warp_m = (warp & 3) * 32;
    const int warp_n = (warp >> 2) * 32;
    const int m0 = blockIdx.y * 128;
    const int n0 = blockIdx.x * 64;

    float acc[2][4][4];
    #pragma unroll
    for (int a = 0; a < 2; a++)
        #pragma unroll
        for (int b = 0; b < 4; b++)
            #pragma unroll
            for (int c = 0; c < 4; c++) acc[a][b][c] = 0.f;

    for (int k0 = 0; k0 < CDIM; k0 += 32) {
        #pragma unroll
        for (int it = 0; it < 4; it++) {
            int idx = tid + it * 256;
            int r = idx >> 3, c4 = (idx & 7) * 4;
            float4 f = *(const float4*)(Ap + (size_t)(m0 + r) * CDIM + k0 + c4);
            *(float4*)&As[r][c4] = tf32_rna4(f);
        }
        #pragma unroll
        for (int it = 0; it < 2; it++) {
            int idx = tid + it * 256;
            int r = idx >> 3, c4 = (idx & 7) * 4;
            float4 f = *(const float4*)(W + (size_t)(n0 + r) * CDIM + k0 + c4);
            *(float4*)&Bs[r][c4] = tf32_rna4(f);
        }
        __syncthreads();

        #pragma unroll
        for (int kk = 0; kk < 32; kk += 8) {
            unsigned af[2][4], bf[4][2];
            #pragma unroll
            for (int mi = 0; mi < 2; mi++) {
                int r = warp_m + mi * 16;
                af[mi][0] = __float_as_uint(As[r + gID    ][kk + tig    ]);
                af[mi][1] = __float_as_uint(As[r + gID + 8][kk + tig    ]);
                af[mi][2] = __float_as_uint(As[r + gID    ][kk + tig + 4]);
                af[mi][3] = __float_as_uint(As[r + gID + 8][kk + tig + 4]);
            }
            #pragma unroll
            for (int ni = 0; ni < 4; ni++) {
                int r = warp_n + ni * 8 + gID;
                bf[ni][0] = __float_as_uint(Bs[r][kk + tig    ]);
                bf[ni][1] = __float_as_uint(Bs[r][kk + tig + 4]);
            }
            #pragma unroll
            for (int mi = 0; mi < 2; mi++)
                #pragma unroll
                for (int ni = 0; ni < 4; ni++)
                    MMA_TF32(acc[mi][ni][0], acc[mi][ni][1],
                             acc[mi][ni][2], acc[mi][ni][3],
                             af[mi][0], af[mi][1], af[mi][2], af[mi][3],
                             bf[ni][0], bf[ni][1]);
        }
        __syncthreads();
    }

    #pragma unroll
    for (int mi = 0; mi < 2; mi++)
        #pragma unroll
        for (int ni = 0; ni < 4; ni++)
            #pragma unroll
            for (int c = 0; c < 4; c++) {
                int row = m0 + warp_m + mi * 16 + gID + ((c >= 2) ? 8 : 0);
                int col = n0 + warp_n + ni * 8 + 2 * tig + (c & 1);
                float v = acc[mi][ni][c] + bias[col];
                if (MODE == 0) {
                    int part = col >> 8;
                    int cc = col & 255;
                    int h = cc >> 5, d = cc & 31;
                    int b = row / NTOK;
                    int i = row - b * NTOK;
                    if (part == 0) v *= QSCALE;
                    float* dst = (part == 0) ? g_q : (part == 1) ? g_k : g_v;
                    dst[(((size_t)b * HEADS + h) * NTOK + i) * HD + d] = v;
                } else {
                    out[(size_t)row * CDIM + col] = v;
                }
            }
}

// ============================================================================
// Attention (tensor-core): one block per (b,h), 128 threads = 4 warps.
// S = q@k^T (64x64x32 tf32 MMA), fused bias+mask+softmax in registers,
// O = P@V (64x32x56 tf32 MMA, V staged transposed). P smem aliases q/k smem
// (row stride 66 words: 64*66=4224 <= 2*64*36=4608 floats available).
// ============================================================================
__global__ __launch_bounds__(128)
void attn_kernel(const float* __restrict__ mask,
                 const float* __restrict__ bias_table)
{
    __shared__ float qk[2][64][36];        // [0]=q rows, [1]=k rows (tf32)
    __shared__ float vb[HD][68];           // v transposed: vb[d][j] (tf32)
    float (*P)[66] = (float(*)[66])&qk[0][0][0];   // aliased after MMA1

    const int b   = blockIdx.x;
    const int h   = blockIdx.y;
    const int tid = threadIdx.x;
    const int warp = tid >> 5;
    const int lane = tid & 31;
    const int gID  = lane >> 2;
    const int tig  = lane & 3;

    const size_t base = ((size_t)b * HEADS + h) * NTOK * HD;

    // ---- stage q, k (49 rows x 8 float4 = 392 vectors) ----
    for (int idx = tid; idx < 392; idx += 128) {
        int r = idx >> 3, c4 = (idx & 7) * 4;
        float4 fq = *(const float4*)(g_q + base + (size_t)r * HD + c4);
        float4 fk = *(const float4*)(g_k + base + (size_t)r * HD + c4);
        *(float4*)&qk[0][r][c4] = tf32_rna4(fq);
        *(float4*)&qk[1][r][c4] = tf32_rna4(fk);
    }
    // ---- stage v transposed; zero pad cols j=49..56 ----
    for (int idx = tid; idx < 256; idx += 128) {
        int d = idx >> 3, j = 49 + (idx & 7);
        if (j < 57) vb[d][j] = 0.f;
    }
    for (int idx = tid; idx < 392; idx += 128) {
        int j = idx >> 3, c4 = (idx & 7) * 4;
        float4 f = tf32_rna4(*(const float4*)(g_v + base + (size_t)j * HD + c4));
        vb[c4 + 0][j] = f.x;
        vb[c4 + 1][j] = f.y;
        vb[c4 + 2][j] = f.z;
        vb[c4 + 3][j] = f.w;
    }
    __syncthreads();

    // ---- MMA1: S[64][64] = q @ k^T, warp owns rows warp*16..+15 ----
    float acc[8][4];
    #pragma unroll
    for (int ni = 0; ni < 8; ni++)
        #pragma unroll
        for (int c = 0; c < 4; c++) acc[ni][c] = 0.f;

    const int rm = warp * 16;
    #pragma unroll
    for (int kk = 0; kk < 32; kk += 8) {
        unsigned a0 = __float_as_uint(qk[0][rm + gID    ][kk + tig    ]);
        unsigned a1 = __float_as_uint(qk[0][rm + gID + 8][kk + tig    ]);
        unsigned a2 = __float_as_uint(qk[0][rm + gID    ][kk + tig + 4]);
        unsigned a3 = __float_as_uint(qk[0][rm + gID + 8][kk + tig + 4]);
        #pragma unroll
        for (int ni = 0; ni < 8; ni++) {
            unsigned b0 = __float_as_uint(qk[1][ni * 8 + gID][kk + tig    ]);
            unsigned b1 = __float_as_uint(qk[1][ni * 8 + gID][kk + tig + 4]);
            MMA_TF32(acc[ni][0], acc[ni][1], acc[ni][2], acc[ni][3],
                     a0, a1, a2, a3, b0, b1);
        }
    }

    // ---- bias + mask + softmax (rows i0 = rm+gID, i1 = i0+8) ----
    // Invalid rows/cols are REPLACED by -1e30 (also kills any NaN garbage
    // from unstaged SMEM rows 49..63 that fed the MMA).
    const int i0 = rm + gID, i1 = i0 + 8;
    const bool v0 = i0 < NTOK, v1 = i1 < NTOK;
    const float* __restrict__ mrow0 =
        mask + (size_t)(b & (NW - 1)) * (NTOK * NTOK) + i0 * NTOK;
    const float* __restrict__ mrow1 = mrow0 + 8 * NTOK;
    const int ci00 = i0 / 7, ci01 = i0 - ci00 * 7;
    const int ci10 = i1 / 7, ci11 = i1 - ci10 * 7;

    #pragma unroll
    for (int ni = 0; ni < 8; ni++)
        #pragma unroll
        for (int half = 0; half < 2; half++) {
            int j = ni * 8 + 2 * tig + half;
            bool okj = j < NTOK;
            int cj0 = j / 7, cj1 = j - cj0 * 7;
            float bz0 = 0.f, bz1 = 0.f;
            if (okj) {
                if (v0) bz0 = __ldg(bias_table + ((ci00 - cj0 + 6) * 13 + (ci01 - cj1 + 6)) * HEADS + h)
                            + __ldg(mrow0 + j);
                if (v1) bz1 = __ldg(bias_table + ((ci10 - cj0 + 6) * 13 + (ci11 - cj1 + 6)) * HEADS + h)
                            + __ldg(mrow1 + j);
            }
            acc[ni][half]     = (okj && v0) ? acc[ni][half]     + bz0 : -1e30f;
            acc[ni][half + 2] = (okj && v1) ? acc[ni][half + 2] + bz1 : -1e30f;
        }

    float mx0 = -1e30f, mx1 = -1e30f;
    #pragma unroll
    for (int ni = 0; ni < 8; ni++) {
        mx0 = fmaxf(mx0, fmaxf(acc[ni][0], acc[ni][1]));
        mx1 = fmaxf(mx1, fmaxf(acc[ni][2], acc[ni][3]));
    }
    #pragma unroll
    for (int s = 1; s <= 2; s <<= 1) {
        mx0 = fmaxf(mx0, __shfl_xor_sync(0xffffffff, mx0, s));
        mx1 = fmaxf(mx1, __shfl_xor_sync(0xffffffff, mx1, s));
    }
    float sm0 = 0.f, sm1 = 0.f;
    #pragma unroll
    for (int ni = 0; ni < 8; ni++) {
        acc[ni][0] = __expf(acc[ni][0] - mx0);
        acc[ni][1] = __expf(acc[ni][1] - mx0);
        acc[ni][2] = __expf(acc[ni][2] - mx1);
        acc[ni][3] = __expf(acc[ni][3] - mx1);
        sm0 += acc[ni][0] + acc[ni][1];
        sm1 += acc[ni][2] + acc[ni][3];
    }
    #pragma unroll
    for (int s = 1; s <= 2; s <<= 1) {
        sm0 += __shfl_xor_sync(0xffffffff, sm0, s);
        sm1 += __shfl_xor_sync(0xffffffff, sm1, s);
    }
    const float inv0 = 1.f / sm0, inv1 = 1.f / sm1;

    __syncthreads();   // all warps done reading qk before P alias write

    #pragma unroll
    for (int ni = 0; ni < 8; ni++) {
        int j0 = ni * 8 + 2 * tig;       // up to 62; row stride 66 is safe
        float2 p0 = make_float2(__uint_as_float(tf32_rna(acc[ni][0] * inv0)),
                                __uint_as_float(tf32_rna(acc[ni][1] * inv0)));
        float2 p1 = make_float2(__uint_as_float(tf32_rna(acc[ni][2] * inv1)),
                                __uint_as_float(tf32_rna(acc[ni][3] * inv1)));
        *(float2*)&P[i0][j0] = p0;
        *(float2*)&P[i1][j0] = p1;
    }
    __syncthreads();

    // ---- MMA2: O[64][32] = P @ V  (K = 56; P cols 49..55 are exact zeros) ----
    float acc2[4][4];
    #pragma unroll
    for (int ni = 0; ni < 4; ni++)
        #pragma unroll
        for (int c = 0; c < 4; c++) acc2[ni][c] = 0.f;

    #pragma unroll
    for (int kk = 0; kk < 56; kk += 8) {
        unsigned a0 = __float_as_uint(P[rm + gID    ][kk + tig    ]);
        unsigned a1 = __float_as_uint(P[rm + gID + 8][kk + tig    ]);
        unsigned a2 = __float_as_uint(P[rm + gID    ][kk + tig + 4]);
        unsigned a3 = __float_as_uint(P[rm + gID + 8][kk + tig + 4]);
        #pragma unroll
        for (int ni = 0; ni < 4; ni++) {
            unsigned b0 = __float_as_uint(vb[ni * 8 + gID][kk + tig    ]);
            unsigned b1 = __float_as_uint(vb[ni * 8 + gID][kk + tig + 4]);
            MMA_TF32(acc2[ni][0], acc2[ni][1], acc2[ni][2], acc2[ni][3],
                     a0, a1, a2, a3, b0, b1);
        }
    }

    // ---- store O to g_att[b, i, h*32+d] ----
    #pragma unroll
    for (int ni = 0; ni < 4; ni++) {
        int d0 = ni * 8 + 2 * tig;
        if (v0) {
            float* p = g_att + (((size_t)b * NTOK + i0) * HEADS + h) * HD + d0;
            *(float2*)p = make_float2(acc2[ni][0], acc2[ni][1]);
        }
        if (v1) {
            float* p = g_att + (((size_t)b * NTOK + i1) * HEADS + h) * HD + d0;
            *(float2*)p = make_float2(acc2[ni][2], acc2[ni][3]);
        }
    }
}

// ============================================================================
// launch
// ============================================================================
extern "C" void kernel_launch(void* const* d_in, const int* in_sizes, int n_in,
                              void* d_out, int out_size)
{
    const float* x          = (const float*)d_in[0];
    const float* mask       = (const float*)d_in[1];
    const float* qkv_w      = (const float*)d_in[2];
    const float* qkv_b      = (const float*)d_in[3];
    const float* proj_w     = (const float*)d_in[4];
    const float* proj_b     = (const float*)d_in[5];
    const float* bias_table = (const float*)d_in[6];
    float* out = (float*)d_out;

    gemm_tf32_kernel<0><<<dim3(768 / 64, MROWS / 128), 256>>>(x, qkv_w, qkv_b, nullptr);
    attn_kernel<<<dim3(BWIN, HEADS), 128>>>(mask, bias_table);
    gemm_tf32_kernel<1><<<dim3(CDIM / 64, MROWS / 128), 256>>>(nullptr, proj_w, proj_b, out);
}